// round 7
// baseline (speedup 1.0000x reference)
#include <cuda_runtime.h>

#define NW 14
#define NSTATE (1 << NW)        // 16384 amplitudes
#define NTHREADS 1024
#define NWARPS (NTHREADS / 32)

typedef unsigned long long ull;

// ==================== compile-time GF(2) machinery ====================
struct CT {
    unsigned rowA[NW];      // rows of A (virtual-bit parities)
    unsigned colAinv[NW];   // columns of A^-1 (pair masks)
    unsigned rowA2[NW];     // rows of A^2 (measurement parity masks)
    int pos[4][12];         // complement unit positions per pass
    unsigned swzM[3][16];   // swz(coset mask M_u) per 4-bit pass
    unsigned baseM[3][4];   // rowA rows for base parities per pass
    unsigned swzF[4];       // final pass: swz of {0, m0, m1, m0^m1}
    int sel[NW];            // Walsh selector per wire (2 bits)
    unsigned cw[NW];        // rowA2[13-w]
};

constexpr unsigned ctswz(unsigned y) { return y ^ ((y >> 4) & 0xFu); }
constexpr int ctpar(unsigned v) { int p = 0; while (v) { p ^= (int)(v & 1u); v >>= 1; } return p; }
constexpr int ctpop(unsigned v) { int p = 0; while (v) { p += (int)(v & 1u); v >>= 1; } return p; }

constexpr bool invOK(const unsigned* cols, int k, unsigned T) {
    int rows[4] = {0, 0, 0, 0}; int n = 0;
    for (int p = 0; p < NW; ++p) if ((T >> p) & 1u) { if (n < 4) rows[n] = p; ++n; }
    if (n != k) return false;
    unsigned mat[4] = {0, 0, 0, 0};
    for (int i = 0; i < k; ++i) {
        unsigned m = 0;
        for (int j = 0; j < k; ++j) m |= ((cols[j] >> rows[i]) & 1u) << j;
        mat[i] = m;
    }
    for (int c = 0; c < k; ++c) {
        int piv = -1;
        for (int rr = c; rr < k; ++rr) if ((mat[rr] >> c) & 1u) { piv = rr; break; }
        if (piv < 0) return false;
        unsigned t = mat[c]; mat[c] = mat[piv]; mat[piv] = t;
        for (int rr = 0; rr < k; ++rr)
            if (rr != c && ((mat[rr] >> c) & 1u)) mat[rr] ^= mat[c];
    }
    return true;
}

constexpr unsigned chooseT(const unsigned* cols, int k) {
    unsigned fb = 0; bool havefb = false;
    for (unsigned mask = 0; mask < (1u << NW); ++mask) {
        if (ctpop(mask) != k) continue;
        if (!invOK(cols, k, mask)) continue;
        int arr[NW] = {}; int n = 0;
        for (int p = 0; p < NW; ++p) if (!((mask >> p) & 1u)) arr[n++] = p;
        bool cf = arr[0] < 8 && arr[1] < 8 && arr[2] < 8 && arr[3] < 8;
        if (cf) {
            int seen = 0;
            for (int i = 0; i < 4; ++i) {
                int bb = 1 << (arr[i] & 3);
                if (seen & bb) { cf = false; break; }
                seen |= bb;
            }
        }
        if (cf) return mask;
        if (!havefb) { fb = mask; havefb = true; }
    }
    return fb;
}

constexpr CT buildCT() {
    CT g{};
    unsigned R[NW] = {};
    for (int j = 0; j < NW; ++j) R[j] = 1u << j;
    for (int w = 0; w < NW - 1; ++w) R[NW - 2 - w] ^= R[NW - 1 - w];
    R[NW - 1] ^= R[0];
    for (int j = 0; j < NW; ++j) g.rowA[j] = R[j];
    unsigned aug[NW] = {};
    for (int j = 0; j < NW; ++j) aug[j] = R[j] | (1u << (NW + j));
    for (int col = 0; col < NW; ++col) {
        int piv = -1;
        for (int rr = col; rr < NW; ++rr)
            if ((aug[rr] >> col) & 1u) { piv = rr; break; }
        unsigned t = aug[col]; aug[col] = aug[piv]; aug[piv] = t;
        for (int rr = 0; rr < NW; ++rr)
            if (rr != col && ((aug[rr] >> col) & 1u)) aug[rr] ^= aug[col];
    }
    for (int bc = 0; bc < NW; ++bc) {
        unsigned mc = 0;
        for (int j = 0; j < NW; ++j) mc |= ((aug[j] >> (NW + bc)) & 1u) << j;
        g.colAinv[bc] = mc;
    }
    for (int k2 = 0; k2 < NW; ++k2) {
        unsigned rr = 0;
        for (int j = 0; j < NW; ++j) if ((R[k2] >> j) & 1u) rr ^= R[j];
        g.rowA2[k2] = rr;
    }
    const int B0s[3] = {10, 6, 2};
    for (int p = 0; p < 3; ++p) {
        unsigned cols[4] = {};
        for (int i = 0; i < 4; ++i) cols[i] = g.colAinv[B0s[p] + i];
        const unsigned T = chooseT(cols, 4);
        int n = 0;
        for (int q = 0; q < NW; ++q) if (!((T >> q) & 1u)) g.pos[p][n++] = q;
        for (unsigned u = 0; u < 16; ++u) {
            unsigned M = 0;
            for (int i = 0; i < 4; ++i) if ((u >> i) & 1u) M ^= cols[i];
            g.swzM[p][u] = ctswz(M);
        }
        for (int i = 0; i < 4; ++i) g.baseM[p][i] = g.rowA[B0s[p] + i];
    }
    {
        unsigned cols[4] = {g.colAinv[0], g.colAinv[1], 0, 0};
        const unsigned T = chooseT(cols, 2);
        int n = 0;
        for (int q = 0; q < NW; ++q) if (!((T >> q) & 1u)) g.pos[3][n++] = q;
        g.swzF[0] = 0;
        g.swzF[1] = ctswz(cols[0]);
        g.swzF[2] = ctswz(cols[1]);
        g.swzF[3] = ctswz(cols[0] ^ cols[1]);
        for (int w = 0; w < NW; ++w) {
            g.cw[w] = g.rowA2[13 - w];
            const int s0 = ctpar(cols[0] & g.cw[w]);
            const int s1 = ctpar(cols[1] & g.cw[w]);
            g.sel[w] = s0 | (s1 << 1);
        }
    }
    return g;
}

constexpr CT CD = buildCT();

// Sign-delta word for a physical bit: bit w = does flipping that bit flip wire w.
constexpr int dword(int bitpos) {
    int d = 0;
    for (int w = 0; w < NW; ++w) d |= (int)((CD.cw[w] >> bitpos) & 1u) << w;
    return d;
}
// Pre-evaluate at namespace scope (host constexpr) -> plain constants usable in
// device constant-expression contexts (no host-fn call from device code).
constexpr int DW10 = dword(CD.pos[3][10]);
constexpr int DW11 = dword(CD.pos[3][11]);

// Device code sees CD only through template args -> literals in SASS, no LDC.
template<int V> struct IC { static constexpr int v = V; };

// ==================== packed f32x2 helpers ====================
__device__ __forceinline__ ull pk2(float lo, float hi) {
    ull r; asm("mov.b64 %0, {%1, %2};" : "=l"(r) : "f"(lo), "f"(hi)); return r;
}
__device__ __forceinline__ void upk2(ull v, float& lo, float& hi) {
    asm("mov.b64 {%0, %1}, %2;" : "=f"(lo), "=f"(hi) : "l"(v));
}
__device__ __forceinline__ ull fma2(ull a, ull b, ull c) {
    ull d; asm("fma.rn.f32x2 %0, %1, %2, %3;" : "=l"(d) : "l"(a), "l"(b), "l"(c)); return d;
}
__device__ __forceinline__ ull mul2(ull a, ull b) {
    ull d; asm("mul.rn.f32x2 %0, %1, %2;" : "=l"(d) : "l"(a), "l"(b)); return d;
}
__device__ __forceinline__ ull swp(ull a) {
    float x, y; upk2(a, x, y); return pk2(y, x);
}

// Complex butterfly on packed amplitudes:
//   E stored as XX=(Re,Re), NG=(-Im,Im):  E*a = a.*XX + swap(a).*NG
__device__ __forceinline__ void bfly(ull& a0, ull& a1,
                                     ull x00, ull g00, ull x01, ull g01,
                                     ull x10, ull g10, ull x11, ull g11) {
    const ull s0 = swp(a0), s1 = swp(a1);
    ull n0 = fma2(a0, x00, fma2(s0, g00, fma2(a1, x01, mul2(s1, g01))));
    ull n1 = fma2(a0, x10, fma2(s0, g10, fma2(a1, x11, mul2(s1, g11))));
    a0 = n0; a1 = n1;
}

// ==================== scalar helpers (pass 0) ====================
__device__ __forceinline__ float2 cmul(float2 a, float2 b) {
    return make_float2(fmaf(a.x, b.x, -a.y * b.y), fmaf(a.x, b.y, a.y * b.x));
}
__device__ __forceinline__ int dswz(int y) { return y ^ ((y >> 4) & 0xF); }

// r = scatter of tid bits to the pass's complement positions (immediates)
template<int P, int K>
__device__ __forceinline__ int build_r(int tid) {
    int v = ((tid >> K) & 1) << IC<CD.pos[P][K]>::v;
    if constexpr (K > 0) v |= build_r<P, K - 1>(tid);
    return v;
}
template<int P, int U>
__device__ __forceinline__ void coset_ld(ull (&amp)[16], const ull* st, int zb) {
    amp[U] = st[zb ^ IC<(int)CD.swzM[P][U]>::v];
    if constexpr (U < 15) coset_ld<P, U + 1>(amp, st, zb);
}
template<int P, int U>
__device__ __forceinline__ void coset_st(const ull (&amp)[16], ull* st, int zb) {
    st[zb ^ IC<(int)CD.swzM[P][U]>::v] = amp[U];
    if constexpr (U < 15) coset_st<P, U + 1>(amp, st, zb);
}

// One 4-bit gate pass with packed butterflies.
template<int P>
__device__ __forceinline__ void gatepass(ull* state, const float2 (*XX)[4],
                                         const float2 (*NG)[4], int tid)
{
    constexpr int B0 = 10 - 4 * P;
    const int r = build_r<P, 9>(tid);
    const int zb = dswz(r);
    const int b0 = __popc(r & IC<(int)CD.baseM[P][0]>::v) & 1;
    const int b1 = __popc(r & IC<(int)CD.baseM[P][1]>::v) & 1;
    const int b2 = __popc(r & IC<(int)CD.baseM[P][2]>::v) & 1;
    const int b3 = __popc(r & IC<(int)CD.baseM[P][3]>::v) & 1;
    const int base = b0 | (b1 << 1) | (b2 << 2) | (b3 << 3);

    ull amp[16];
    coset_ld<P, 0>(amp, state, zb);
#pragma unroll
    for (int i = 0; i < 4; ++i) {
        const int w = 13 - (B0 + i);
        const int sw = ((base >> i) & 1) ? 3 : 0;   // label swap -> reversed matrix
        const ull* xx = reinterpret_cast<const ull*>(XX[w]);
        const ull* ng = reinterpret_cast<const ull*>(NG[w]);
        const ull x00 = xx[0 ^ sw], g00 = ng[0 ^ sw];
        const ull x01 = xx[1 ^ sw], g01 = ng[1 ^ sw];
        const ull x10 = xx[2 ^ sw], g10 = ng[2 ^ sw];
        const ull x11 = xx[3 ^ sw], g11 = ng[3 ^ sw];
#pragma unroll
        for (int u = 0; u < 16; ++u) {
            if (u & (1 << i)) continue;
            bfly(amp[u], amp[u | (1 << i)], x00, g00, x01, g01, x10, g10, x11, g11);
        }
    }
    coset_st<P, 0>(amp, state, zb);
}

// Build 14-bit signword: bit w = parity(r & cw[w])
template<int W>
__device__ __forceinline__ int signw(int r) {
    int v = (__popc(r & IC<(int)CD.cw[W]>::v) & 1) << W;
    if constexpr (W > 0) v |= signw<W - 1>(r);
    return v;
}
// Accumulate all 14 wires: acc[w] += (-1)^bit_w(swv) * W[sel[w]]
template<int W>
__device__ __forceinline__ void accw(float (&acc)[NW], int swv,
                                     float W0, float W1, float W2, float W3) {
    constexpr int s = IC<CD.sel[W]>::v;
    const float tv = (s == 0) ? W0 : (s == 1) ? W1 : (s == 2) ? W2 : W3;
    const unsigned sg = (((unsigned)swv >> W) & 1u) << 31;
    acc[W] += __int_as_float(__float_as_int(tv) ^ sg);
    if constexpr (W < NW - 1) accw<W + 1>(acc, swv, W0, W1, W2, W3);
}

// ==================== kernel ====================
__global__ __launch_bounds__(NTHREADS, 1)
void qsim_kernel(const float* __restrict__ x, const float* __restrict__ params,
                 float* __restrict__ out)
{
    extern __shared__ float2 state[];      // 16384 float2 = 128 KB
    __shared__ float2 m0V[NW][4];          // layer-0 fused matrices (Re,Im)
    __shared__ float2 mXX[NW][4];          // layer-1: (Re,Re)
    __shared__ float2 mNG[NW][4];          // layer-1: (-Im,Im)
    __shared__ float wsum[NWARPS][NW];

    ull* stateu = reinterpret_cast<ull*>(state);
    const int tid = threadIdx.x;
    const int b = blockIdx.x;

    // ---- fused gate matrices: M = RX * RZ * RY (layer 0 folds in x)
    if (tid < 2 * NW) {
        const int l = tid / NW, w = tid % NW;
        const float* pp = params + (l * NW + w) * 3;
        float th = pp[0] + (l == 0 ? x[b * NW + w] : 0.0f);
        float s, c;   sincosf(0.5f * th, &s, &c);
        float sz, cz; sincosf(0.5f * pp[1], &sz, &cz);
        float sx, cx; sincosf(0.5f * pp[2], &sx, &cx);
        float2 r00 = make_float2(c * cz, -c * sz);
        float2 r01 = make_float2(-s * cz, s * sz);
        float2 r10 = make_float2(s * cz, s * sz);
        float2 r11 = make_float2(c * cz, c * sz);
        float2 M[4];
        M[0] = make_float2(cx * r00.x + sx * r10.y, cx * r00.y - sx * r10.x);
        M[1] = make_float2(cx * r01.x + sx * r11.y, cx * r01.y - sx * r11.x);
        M[2] = make_float2(sx * r00.y + cx * r10.x, -sx * r00.x + cx * r10.y);
        M[3] = make_float2(sx * r01.y + cx * r11.x, -sx * r01.x + cx * r11.y);
        if (l == 0) {
#pragma unroll
            for (int e = 0; e < 4; ++e) m0V[w][e] = M[e];
        } else {
#pragma unroll
            for (int e = 0; e < 4; ++e) {
                mXX[w][e] = make_float2(M[e].x, M[e].x);
                mNG[w][e] = make_float2(-M[e].y, M[e].y);
            }
        }
    }
    __syncthreads();

    // ---- Pass 0: build post-layer-0 product state (no loads, tree expansion)
    {
        const int t = tid;                              // y bits 4..13
        float2 p = m0V[9][(t & 1) ? 2 : 0];             // y bit 4 = wire 9
#pragma unroll
        for (int bb = 5; bb < 14; ++bb) {
            float2 c = m0V[13 - bb][((t >> (bb - 4)) & 1) ? 2 : 0];
            p = cmul(p, c);
        }
        float2 amp[16];
        amp[0] = p;
#pragma unroll
        for (int i = 0; i < 4; ++i) {                   // y bit i = wire 13-i
            const float2 c0 = m0V[13 - i][0], c1 = m0V[13 - i][2];
#pragma unroll
            for (int j = (1 << i) - 1; j >= 0; --j) {
                amp[j | (1 << i)] = cmul(amp[j], c1);
                amp[j] = cmul(amp[j], c0);
            }
        }
        const int sb = dswz(t << 4);                    // swz linear: offsets = j
#pragma unroll
        for (int j = 0; j < 16; ++j) state[sb ^ j] = amp[j];
    }
    __syncthreads();

    // ---- Three 4-bit gate passes (virtual bits {10..13}, {6..9}, {2..5})
    gatepass<0>(stateu, mXX, mNG, tid);
    __syncthreads();
    gatepass<1>(stateu, mXX, mNG, tid);
    __syncthreads();
    gatepass<2>(stateu, mXX, mNG, tid);
    __syncthreads();

    // ---- Final pass: gates on virtual bits {0,1} fused with measurement
    float acc[NW];
#pragma unroll
    for (int w = 0; w < NW; ++w) acc[w] = 0.0f;
    {
        const int r0 = build_r<3, 9>(tid);
        const int sw0 = signw<NW - 1>(r0);
#pragma unroll
        for (int it = 0; it < 4; ++it) {
            int r = r0;
            int swv = sw0;
            if (it & 1) { r ^= 1 << IC<CD.pos[3][10]>::v; swv ^= IC<DW10>::v; }
            if (it & 2) { r ^= 1 << IC<CD.pos[3][11]>::v; swv ^= IC<DW11>::v; }
            const int z = dswz(r);
            const int b0 = __popc(r & IC<(int)CD.rowA[0]>::v) & 1;
            const int b1 = __popc(r & IC<(int)CD.rowA[1]>::v) & 1;
            ull a0 = stateu[z];
            ull a1 = stateu[z ^ IC<(int)CD.swzF[1]>::v];
            ull a2 = stateu[z ^ IC<(int)CD.swzF[2]>::v];
            ull a3 = stateu[z ^ IC<(int)CD.swzF[3]>::v];
            {   // gate wire 13 (virtual bit 0): pairs (a0,a1), (a2,a3)
                const int sw = b0 ? 3 : 0;
                const ull* xx = reinterpret_cast<const ull*>(mXX[13]);
                const ull* ng = reinterpret_cast<const ull*>(mNG[13]);
                const ull x00 = xx[0 ^ sw], g00 = ng[0 ^ sw];
                const ull x01 = xx[1 ^ sw], g01 = ng[1 ^ sw];
                const ull x10 = xx[2 ^ sw], g10 = ng[2 ^ sw];
                const ull x11 = xx[3 ^ sw], g11 = ng[3 ^ sw];
                bfly(a0, a1, x00, g00, x01, g01, x10, g10, x11, g11);
                bfly(a2, a3, x00, g00, x01, g01, x10, g10, x11, g11);
            }
            {   // gate wire 12 (virtual bit 1): pairs (a0,a2), (a1,a3)
                const int sw = b1 ? 3 : 0;
                const ull* xx = reinterpret_cast<const ull*>(mXX[12]);
                const ull* ng = reinterpret_cast<const ull*>(mNG[12]);
                const ull x00 = xx[0 ^ sw], g00 = ng[0 ^ sw];
                const ull x01 = xx[1 ^ sw], g01 = ng[1 ^ sw];
                const ull x10 = xx[2 ^ sw], g10 = ng[2 ^ sw];
                const ull x11 = xx[3 ^ sw], g11 = ng[3 ^ sw];
                bfly(a0, a2, x00, g00, x01, g01, x10, g10, x11, g11);
                bfly(a1, a3, x00, g00, x01, g01, x10, g10, x11, g11);
            }
            float a0x, a0y, a1x, a1y, a2x, a2y, a3x, a3y;
            upk2(a0, a0x, a0y); upk2(a1, a1x, a1y);
            upk2(a2, a2x, a2y); upk2(a3, a3x, a3y);
            const float p0 = fmaf(a0x, a0x, a0y * a0y);
            const float p1 = fmaf(a1x, a1x, a1y * a1y);
            const float p2 = fmaf(a2x, a2x, a2y * a2y);
            const float p3 = fmaf(a3x, a3x, a3y * a3y);
            const float sa = p0 + p1, sb = p0 - p1, sc = p2 + p3, sd = p2 - p3;
            const float W0 = sa + sc, W1 = sb + sd, W2 = sa - sc, W3 = sb - sd;
            accw<0>(acc, swv, W0, W1, W2, W3);
        }
    }

    // ---- block reduction of 14 accumulators
    const int lane = tid & 31, warp = tid >> 5;
#pragma unroll
    for (int w = 0; w < NW; ++w) {
        float v = acc[w];
#pragma unroll
        for (int off = 16; off; off >>= 1) v += __shfl_down_sync(0xFFFFFFFFu, v, off);
        if (lane == 0) wsum[warp][w] = v;
    }
    __syncthreads();
    if (tid < NW) {
        float s = 0.0f;
#pragma unroll
        for (int q = 0; q < NWARPS; ++q) s += wsum[q][tid];
        out[b * NW + tid] = s;
    }
}

// ==================== host side ====================
extern "C" void kernel_launch(void* const* d_in, const int* in_sizes, int n_in,
                              void* d_out, int out_size)
{
    int i_x = 0, i_p = 1;
    if (n_in >= 2 && in_sizes[0] == 2 * NW * 3) { i_x = 1; i_p = 0; }
    const float* x = (const float*)d_in[i_x];
    const float* params = (const float*)d_in[i_p];
    float* out = (float*)d_out;

    const int batch = in_sizes[i_x] / NW;

    cudaFuncSetAttribute(qsim_kernel, cudaFuncAttributeMaxDynamicSharedMemorySize,
                         NSTATE * sizeof(float2));
    qsim_kernel<<<batch, NTHREADS, NSTATE * sizeof(float2)>>>(x, params, out);
}

// round 8
// speedup vs baseline: 1.3589x; 1.3589x over previous
#include <cuda_runtime.h>

#define NW 14
#define NSTATE (1 << NW)        // 16384 amplitudes
#define NTHREADS 512
#define NWARPS (NTHREADS / 32)

// ==================== compile-time GF(2) machinery ====================
// Entangler ring is fixed: A (virtual-bit map), A^-1 (pair masks), A^2
// (measurement parities) and all derived offsets are compile-time constants.
struct CT {
    unsigned rowA[NW];      // rows of A
    unsigned colAinv[NW];   // columns of A^-1 (pair masks)
    unsigned cw[NW];        // rowA2[13-w]: measurement parity masks per wire
    unsigned swzM0[32];     // swz(coset offsets), pass 0 (virtual bits 9..13)
    unsigned swzM1[32];     // pass 1 (virtual bits 4..8)
    unsigned swzM2[16];     // pass 2 (virtual bits 0..3)
    int fw[NW];             // WHT frequency per wire (4 bits)
    int dw13;               // signword delta when physical bit 13 flips
};

constexpr unsigned ctswz(unsigned y) { return y ^ ((y >> 4) & 0xFu); }
constexpr int ctpar(unsigned v) { int p = 0; while (v) { p ^= (int)(v & 1u); v >>= 1; } return p; }

constexpr CT buildCT() {
    CT g{};
    unsigned R[NW] = {};
    for (int j = 0; j < NW; ++j) R[j] = 1u << j;
    // CNOT(w,w+1) w=0..12 then CNOT(13,0); wire w <-> bit 13-w
    for (int w = 0; w < NW - 1; ++w) R[NW - 2 - w] ^= R[NW - 1 - w];
    R[NW - 1] ^= R[0];
    for (int j = 0; j < NW; ++j) g.rowA[j] = R[j];
    // A^-1 via Gauss-Jordan
    unsigned aug[NW] = {};
    for (int j = 0; j < NW; ++j) aug[j] = R[j] | (1u << (NW + j));
    for (int col = 0; col < NW; ++col) {
        int piv = -1;
        for (int rr = col; rr < NW; ++rr)
            if ((aug[rr] >> col) & 1u) { piv = rr; break; }
        unsigned t = aug[col]; aug[col] = aug[piv]; aug[piv] = t;
        for (int rr = 0; rr < NW; ++rr)
            if (rr != col && ((aug[rr] >> col) & 1u)) aug[rr] ^= aug[col];
    }
    for (int bc = 0; bc < NW; ++bc) {
        unsigned mc = 0;
        for (int j = 0; j < NW; ++j) mc |= ((aug[j] >> (NW + bc)) & 1u) << j;
        g.colAinv[bc] = mc;
    }
    // A^2 rows -> per-wire masks
    for (int w = 0; w < NW; ++w) {
        const int k = 13 - w;
        unsigned rr = 0;
        for (int j = 0; j < NW; ++j) if ((R[k] >> j) & 1u) rr ^= R[j];
        g.cw[w] = rr;
    }
    for (unsigned u = 0; u < 32; ++u) {
        unsigned M0 = 0, M1 = 0;
        for (int i = 0; i < 5; ++i) if ((u >> i) & 1u) { M0 ^= g.colAinv[9 + i]; M1 ^= g.colAinv[4 + i]; }
        g.swzM0[u] = ctswz(M0);
        g.swzM1[u] = ctswz(M1);
    }
    for (unsigned u = 0; u < 16; ++u) {
        unsigned M = 0;
        for (int i = 0; i < 4; ++i) if ((u >> i) & 1u) M ^= g.colAinv[i];
        g.swzM2[u] = ctswz(M);
    }
    for (int w = 0; w < NW; ++w) {
        int f = 0;
        for (int i = 0; i < 4; ++i) f |= ctpar(g.colAinv[i] & g.cw[w]) << i;
        g.fw[w] = f;
    }
    g.dw13 = 0;
    for (int w = 0; w < NW; ++w) g.dw13 |= (int)((g.cw[w] >> 13) & 1u) << w;
    return g;
}
constexpr CT CD = buildCT();

// ---- compile-time validation of the pass decomposition ----
constexpr bool checkPass(unsigned posmask, int b0, int k) {
    unsigned v[NW] = {}; int n = 0;
    for (int p = 0; p < NW; ++p) if ((posmask >> p) & 1u) v[n++] = 1u << p;
    for (int i = 0; i < k; ++i) v[n++] = CD.colAinv[b0 + i];
    if (n != NW) return false;
    int rank = 0;
    for (int bit = 0; bit < NW; ++bit) {
        int piv = -1;
        for (int i = rank; i < NW; ++i) if ((v[i] >> bit) & 1u) { piv = i; break; }
        if (piv < 0) continue;
        unsigned t = v[rank]; v[rank] = v[piv]; v[piv] = t;
        for (int i = 0; i < NW; ++i) if (i != rank && ((v[i] >> bit) & 1u)) v[i] ^= v[rank];
        ++rank;
    }
    return rank == NW;
}
static_assert(checkPass(0x01FF, 9, 5), "p0 transversal");   // complement bits 0..8
static_assert(checkPass(0x3E0F, 4, 5), "p1 transversal");   // bits 0..3, 9..13
static_assert(checkPass(0x3FF0, 0, 4), "p2 transversal");   // bits 4..13
// p0 masks are exactly adjacent-bit pairs in bits 8..13 (C-table assumption)
static_assert(CD.colAinv[9] == 0x300 && CD.colAinv[10] == 0x600 &&
              CD.colAinv[11] == 0xC00 && CD.colAinv[12] == 0x1800 &&
              CD.colAinv[13] == 0x3000, "p0 masks");
// base-parity collapses
static_assert((CD.rowA[9] & 0x1FF) == 0 && (CD.rowA[10] & 0x1FF) == 0 &&
              (CD.rowA[11] & 0x1FF) == 0 && (CD.rowA[12] & 0x1FF) == 0 &&
              (CD.rowA[13] & 0x1FF) == 0x1FF, "p0 bases");
static_assert((CD.rowA[4] & 0x3E0F) == 0x3E00 && (CD.rowA[5] & 0x3E0F) == 0x3E00 &&
              (CD.rowA[6] & 0x3E0F) == 0x3E00 && (CD.rowA[7] & 0x3E0F) == 0x3E00 &&
              (CD.rowA[8] & 0x3E0F) == 0x3E00, "p1 bases");
static_assert((CD.rowA[0] & 0x3FF0) == 0x3FF0 && (CD.rowA[1] & 0x3FF0) == 0x3FF0 &&
              (CD.rowA[2] & 0x3FF0) == 0x3FF0 && (CD.rowA[3] & 0x3FF0) == 0x3FF0, "p2 bases");

// Device code sees CD only through template args -> literals in SASS.
template<int V> struct IC { static constexpr int v = V; };

// ==================== device helpers ====================
__device__ __forceinline__ float2 cmul(float2 a, float2 b) {
    return make_float2(fmaf(a.x, b.x, -a.y * b.y), fmaf(a.x, b.y, a.y * b.x));
}
__device__ __forceinline__ float2 cmadd(float2 acc, float2 a, float2 b) {
    acc.x = fmaf(a.x, b.x, fmaf(-a.y, b.y, acc.x));
    acc.y = fmaf(a.x, b.y, fmaf(a.y, b.x, acc.y));
    return acc;
}
__device__ __forceinline__ int dswz(int y) { return y ^ ((y >> 4) & 0xF); }

__device__ __forceinline__ void bfly(float2& a0, float2& a1,
                                     float2 E00, float2 E01, float2 E10, float2 E11) {
    float2 n0 = cmul(E00, a0); n0 = cmadd(n0, E01, a1);
    float2 n1 = cmul(E10, a0); n1 = cmadd(n1, E11, a1);
    a0 = n0; a1 = n1;
}

template<int P, int U, int NU>
__device__ __forceinline__ void coset_ld(float2* amp, const float2* st, int zb) {
    if constexpr (P == 0)      amp[U] = st[zb ^ IC<(int)CD.swzM0[U]>::v];
    else if constexpr (P == 1) amp[U] = st[zb ^ IC<(int)CD.swzM1[U]>::v];
    else                       amp[U] = st[zb ^ IC<(int)CD.swzM2[U]>::v];
    if constexpr (U + 1 < NU) coset_ld<P, U + 1, NU>(amp, st, zb);
}
template<int P, int U, int NU>
__device__ __forceinline__ void coset_st(const float2* amp, float2* st, int zb) {
    if constexpr (P == 0)      st[zb ^ IC<(int)CD.swzM0[U]>::v] = amp[U];
    else if constexpr (P == 1) st[zb ^ IC<(int)CD.swzM1[U]>::v] = amp[U];
    else                       st[zb ^ IC<(int)CD.swzM2[U]>::v] = amp[U];
    if constexpr (U + 1 < NU) coset_st<P, U + 1, NU>(amp, st, zb);
}

// signword: bit w = parity(r & cw[w])
template<int W>
__device__ __forceinline__ int signw(int r) {
    int v = (__popc(r & IC<(int)CD.cw[W]>::v) & 1) << W;
    if constexpr (W > 0) v |= signw<W - 1>(r);
    return v;
}
// acc[w] += (-1)^bit_w(swv) * WHT[fw[w]]
template<int W>
__device__ __forceinline__ void accw(float (&acc)[NW], int swv, const float (&Wv)[16]) {
    const float tv = Wv[IC<CD.fw[W]>::v];
    const unsigned sg = (((unsigned)swv >> W) & 1u) << 31;
    acc[W] += __int_as_float(__float_as_int(tv) ^ sg);
    if constexpr (W < NW - 1) accw<W + 1>(acc, swv, Wv);
}

// ==================== kernel ====================
__global__ __launch_bounds__(NTHREADS, 1)
void qsim_kernel(const float* __restrict__ x, const float* __restrict__ params,
                 float* __restrict__ out)
{
    extern __shared__ float2 state[];      // 16384 float2 = 128 KB
    __shared__ float2 m0V[NW][4];          // layer-0 fused 2x2 (incl. x)
    __shared__ float2 m1V[NW][4];          // layer-1 fused 2x2
    __shared__ float2 Cs[32];              // p0 coset table over bits 9..13
    __shared__ float wsum[NWARPS][NW];

    const int tid = threadIdx.x;
    const int b = blockIdx.x;

    // ---- fused gate matrices: M = RX * RZ * RY (layer 0 folds in x)
    if (tid < 2 * NW) {
        const int l = tid / NW, w = tid % NW;
        const float* pp = params + (l * NW + w) * 3;
        float th = pp[0] + (l == 0 ? x[b * NW + w] : 0.0f);
        float s, c;   sincosf(0.5f * th, &s, &c);
        float sz, cz; sincosf(0.5f * pp[1], &sz, &cz);
        float sx, cx; sincosf(0.5f * pp[2], &sx, &cx);
        float2 r00 = make_float2(c * cz, -c * sz);
        float2 r01 = make_float2(-s * cz, s * sz);
        float2 r10 = make_float2(s * cz, s * sz);
        float2 r11 = make_float2(c * cz, c * sz);
        float2 (*dst)[4] = (l == 0) ? m0V : m1V;
        dst[w][0] = make_float2(cx * r00.x + sx * r10.y, cx * r00.y - sx * r10.x);
        dst[w][1] = make_float2(cx * r01.x + sx * r11.y, cx * r01.y - sx * r11.x);
        dst[w][2] = make_float2(sx * r00.y + cx * r10.x, -sx * r00.x + cx * r10.y);
        dst[w][3] = make_float2(sx * r01.y + cx * r11.x, -sx * r01.x + cx * r11.y);
    }
    __syncthreads();

    // ---- C table: product over bits 9..13 for each p0 coset coordinate u
    if (tid < 32) {
        const int u0 = tid & 1, u1 = (tid >> 1) & 1, u2 = (tid >> 2) & 1,
                  u3 = (tid >> 3) & 1, u4 = (tid >> 4) & 1;
        float2 c = m0V[4][(u0 ^ u1) ? 2 : 0];    // bit 9  -> wire 4
        c = cmul(c, m0V[3][(u1 ^ u2) ? 2 : 0]);  // bit 10 -> wire 3
        c = cmul(c, m0V[2][(u2 ^ u3) ? 2 : 0]);  // bit 11 -> wire 2
        c = cmul(c, m0V[1][(u3 ^ u4) ? 2 : 0]);  // bit 12 -> wire 1
        c = cmul(c, m0V[0][u4 ? 2 : 0]);         // bit 13 -> wire 0
        Cs[tid] = c;
    }
    __syncthreads();

    // ---- Pass 0: product state for this coset + gates on virtual bits 9..13
    {
        const int r = tid;                       // complement bits 0..8
        const int zb = dswz(r);
        float2 P = m0V[13][(r & 1) ? 2 : 0];
#pragma unroll
        for (int j = 1; j < 8; ++j) P = cmul(P, m0V[13 - j][((r >> j) & 1) ? 2 : 0]);
        const int r8 = (r >> 8) & 1;
        const float2 P0 = cmul(P, m0V[5][r8 ? 2 : 0]);   // u0=0
        const float2 P1 = cmul(P, m0V[5][r8 ? 0 : 2]);   // u0=1 (bit 8 flipped)
        float2 amp[32];
#pragma unroll
        for (int u = 0; u < 32; ++u) amp[u] = cmul((u & 1) ? P1 : P0, Cs[u]);
        // stages 0..3: wires 4..1, swap-free (base parities = 0)
#pragma unroll
        for (int i = 0; i < 4; ++i) {
            const int w = 4 - i;
            const float2 E00 = m1V[w][0], E01 = m1V[w][1];
            const float2 E10 = m1V[w][2], E11 = m1V[w][3];
#pragma unroll
            for (int u = 0; u < 32; ++u) {
                if (u & (1 << i)) continue;
                bfly(amp[u], amp[u | (1 << i)], E00, E01, E10, E11);
            }
        }
        {   // stage 4: wire 0, swap = parity(r)
            const int sw = (__popc(r) & 1) ? 3 : 0;
            const float2 E00 = m1V[0][0 ^ sw], E01 = m1V[0][1 ^ sw];
            const float2 E10 = m1V[0][2 ^ sw], E11 = m1V[0][3 ^ sw];
#pragma unroll
            for (int u = 0; u < 16; ++u)
                bfly(amp[u], amp[u | 16], E00, E01, E10, E11);
        }
        coset_st<0, 0, 32>(amp, state, zb);
    }
    __syncthreads();

    // ---- Pass 1: gates on virtual bits 4..8 (wires 9..5)
    {
        const int r = (tid & 0xF) | ((tid >> 4) << 9);   // bits 0..3, 9..13
        const int zb = dswz(r);
        const int sw = (__popc(tid >> 4) & 1) ? 3 : 0;   // shared by all 5 stages
        float2 amp[32];
        coset_ld<1, 0, 32>(amp, state, zb);
#pragma unroll
        for (int i = 0; i < 5; ++i) {
            const int w = 9 - i;
            const float2 E00 = m1V[w][0 ^ sw], E01 = m1V[w][1 ^ sw];
            const float2 E10 = m1V[w][2 ^ sw], E11 = m1V[w][3 ^ sw];
#pragma unroll
            for (int u = 0; u < 32; ++u) {
                if (u & (1 << i)) continue;
                bfly(amp[u], amp[u | (1 << i)], E00, E01, E10, E11);
            }
        }
        coset_st<1, 0, 32>(amp, state, zb);
    }
    __syncthreads();

    // ---- Pass 2: gates on virtual bits 0..3 (wires 13..10) fused w/ measurement
    float acc[NW];
#pragma unroll
    for (int w = 0; w < NW; ++w) acc[w] = 0.0f;
    {
        const int swv0 = signw<NW - 1>(tid << 4);
#pragma unroll
        for (int it = 0; it < 2; ++it) {
            const int r = (tid << 4) | (it << 13);       // bits 4..13
            const int zb = dswz(r);
            const int sw = ((__popc(tid) + it) & 1) ? 3 : 0;  // all 4 stages
            float2 amp[16];
            coset_ld<2, 0, 16>(amp, state, zb);
#pragma unroll
            for (int i = 0; i < 4; ++i) {
                const int w = 13 - i;
                const float2 E00 = m1V[w][0 ^ sw], E01 = m1V[w][1 ^ sw];
                const float2 E10 = m1V[w][2 ^ sw], E11 = m1V[w][3 ^ sw];
#pragma unroll
                for (int u = 0; u < 16; ++u) {
                    if (u & (1 << i)) continue;
                    bfly(amp[u], amp[u | (1 << i)], E00, E01, E10, E11);
                }
            }
            float Wv[16];
#pragma unroll
            for (int u = 0; u < 16; ++u)
                Wv[u] = fmaf(amp[u].x, amp[u].x, amp[u].y * amp[u].y);
            // 16-point WHT: Wv[f] = sum_u (-1)^{popc(f&u)} p[u]
#pragma unroll
            for (int d = 1; d < 16; d <<= 1) {
#pragma unroll
                for (int u = 0; u < 16; ++u) {
                    if (u & d) continue;
                    const float a = Wv[u], bb = Wv[u | d];
                    Wv[u] = a + bb; Wv[u | d] = a - bb;
                }
            }
            const int swv = it ? (swv0 ^ IC<CD.dw13>::v) : swv0;
            accw<0>(acc, swv, Wv);
        }
    }

    // ---- block reduction of 14 accumulators
    const int lane = tid & 31, warp = tid >> 5;
#pragma unroll
    for (int w = 0; w < NW; ++w) {
        float v = acc[w];
#pragma unroll
        for (int off = 16; off; off >>= 1) v += __shfl_down_sync(0xFFFFFFFFu, v, off);
        if (lane == 0) wsum[warp][w] = v;
    }
    __syncthreads();
    if (tid < NW) {
        float s = 0.0f;
#pragma unroll
        for (int q = 0; q < NWARPS; ++q) s += wsum[q][tid];
        out[b * NW + tid] = s;
    }
}

// ==================== host side ====================
extern "C" void kernel_launch(void* const* d_in, const int* in_sizes, int n_in,
                              void* d_out, int out_size)
{
    int i_x = 0, i_p = 1;
    if (n_in >= 2 && in_sizes[0] == 2 * NW * 3) { i_x = 1; i_p = 0; }
    const float* x = (const float*)d_in[i_x];
    const float* params = (const float*)d_in[i_p];
    float* out = (float*)d_out;

    const int batch = in_sizes[i_x] / NW;

    cudaFuncSetAttribute(qsim_kernel, cudaFuncAttributeMaxDynamicSharedMemorySize,
                         NSTATE * sizeof(float2));
    qsim_kernel<<<batch, NTHREADS, NSTATE * sizeof(float2)>>>(x, params, out);
}

// round 9
// speedup vs baseline: 1.5370x; 1.1311x over previous
#include <cuda_runtime.h>

#define NW 14
#define NSTATE (1 << NW)        // 16384 amplitudes
#define NTHREADS 512
#define NWARPS (NTHREADS / 32)

// ==================== compile-time GF(2) machinery ====================
struct CT {
    unsigned rowA[NW];      // rows of A
    unsigned colAinv[NW];   // columns of A^-1 (pair masks)
    unsigned cw[NW];        // rowA2[13-w]: measurement parity masks per wire
    unsigned swzM0[32];     // swz(coset offsets), pass 0 (virtual bits 9..13)
    unsigned swzM1[32];     // pass 1 (virtual bits 4..8)
    unsigned swzM2[16];     // pass 2 (virtual bits 0..3)
    int fw[NW];             // WHT frequency per wire (4 bits)
    int dw13;               // signword delta when physical bit 13 flips
};

constexpr unsigned ctswz(unsigned y) { return y ^ ((y >> 4) & 0xFu); }
constexpr int ctpar(unsigned v) { int p = 0; while (v) { p ^= (int)(v & 1u); v >>= 1; } return p; }

constexpr CT buildCT() {
    CT g{};
    unsigned R[NW] = {};
    for (int j = 0; j < NW; ++j) R[j] = 1u << j;
    // CNOT(w,w+1) w=0..12 then CNOT(13,0); wire w <-> bit 13-w
    for (int w = 0; w < NW - 1; ++w) R[NW - 2 - w] ^= R[NW - 1 - w];
    R[NW - 1] ^= R[0];
    for (int j = 0; j < NW; ++j) g.rowA[j] = R[j];
    unsigned aug[NW] = {};
    for (int j = 0; j < NW; ++j) aug[j] = R[j] | (1u << (NW + j));
    for (int col = 0; col < NW; ++col) {
        int piv = -1;
        for (int rr = col; rr < NW; ++rr)
            if ((aug[rr] >> col) & 1u) { piv = rr; break; }
        unsigned t = aug[col]; aug[col] = aug[piv]; aug[piv] = t;
        for (int rr = 0; rr < NW; ++rr)
            if (rr != col && ((aug[rr] >> col) & 1u)) aug[rr] ^= aug[col];
    }
    for (int bc = 0; bc < NW; ++bc) {
        unsigned mc = 0;
        for (int j = 0; j < NW; ++j) mc |= ((aug[j] >> (NW + bc)) & 1u) << j;
        g.colAinv[bc] = mc;
    }
    for (int w = 0; w < NW; ++w) {
        const int k = 13 - w;
        unsigned rr = 0;
        for (int j = 0; j < NW; ++j) if ((R[k] >> j) & 1u) rr ^= R[j];
        g.cw[w] = rr;
    }
    for (unsigned u = 0; u < 32; ++u) {
        unsigned M0 = 0, M1 = 0;
        for (int i = 0; i < 5; ++i) if ((u >> i) & 1u) { M0 ^= g.colAinv[9 + i]; M1 ^= g.colAinv[4 + i]; }
        g.swzM0[u] = ctswz(M0);
        g.swzM1[u] = ctswz(M1);
    }
    for (unsigned u = 0; u < 16; ++u) {
        unsigned M = 0;
        for (int i = 0; i < 4; ++i) if ((u >> i) & 1u) M ^= g.colAinv[i];
        g.swzM2[u] = ctswz(M);
    }
    for (int w = 0; w < NW; ++w) {
        int f = 0;
        for (int i = 0; i < 4; ++i) f |= ctpar(g.colAinv[i] & g.cw[w]) << i;
        g.fw[w] = f;
    }
    g.dw13 = 0;
    for (int w = 0; w < NW; ++w) g.dw13 |= (int)((g.cw[w] >> 13) & 1u) << w;
    return g;
}
constexpr CT CD = buildCT();

// ---- compile-time validation of the pass decomposition ----
constexpr bool checkPass(unsigned posmask, int b0, int k) {
    unsigned v[NW] = {}; int n = 0;
    for (int p = 0; p < NW; ++p) if ((posmask >> p) & 1u) v[n++] = 1u << p;
    for (int i = 0; i < k; ++i) v[n++] = CD.colAinv[b0 + i];
    if (n != NW) return false;
    int rank = 0;
    for (int bit = 0; bit < NW; ++bit) {
        int piv = -1;
        for (int i = rank; i < NW; ++i) if ((v[i] >> bit) & 1u) { piv = i; break; }
        if (piv < 0) continue;
        unsigned t = v[rank]; v[rank] = v[piv]; v[piv] = t;
        for (int i = 0; i < NW; ++i) if (i != rank && ((v[i] >> bit) & 1u)) v[i] ^= v[rank];
        ++rank;
    }
    return rank == NW;
}
static_assert(checkPass(0x01FF, 9, 5), "p0 transversal");
static_assert(checkPass(0x3E0F, 4, 5), "p1 transversal");
static_assert(checkPass(0x3FF0, 0, 4), "p2 transversal");
static_assert(CD.colAinv[9] == 0x300 && CD.colAinv[10] == 0x600 &&
              CD.colAinv[11] == 0xC00 && CD.colAinv[12] == 0x1800 &&
              CD.colAinv[13] == 0x3000, "p0 masks");
static_assert((CD.rowA[9] & 0x1FF) == 0 && (CD.rowA[10] & 0x1FF) == 0 &&
              (CD.rowA[11] & 0x1FF) == 0 && (CD.rowA[12] & 0x1FF) == 0 &&
              (CD.rowA[13] & 0x1FF) == 0x1FF, "p0 bases");
static_assert((CD.rowA[4] & 0x3E0F) == 0x3E00 && (CD.rowA[5] & 0x3E0F) == 0x3E00 &&
              (CD.rowA[6] & 0x3E0F) == 0x3E00 && (CD.rowA[7] & 0x3E0F) == 0x3E00 &&
              (CD.rowA[8] & 0x3E0F) == 0x3E00, "p1 bases");
static_assert((CD.rowA[0] & 0x3FF0) == 0x3FF0 && (CD.rowA[1] & 0x3FF0) == 0x3FF0 &&
              (CD.rowA[2] & 0x3FF0) == 0x3FF0 && (CD.rowA[3] & 0x3FF0) == 0x3FF0, "p2 bases");

template<int V> struct IC { static constexpr int v = V; };

// ==================== device helpers ====================
__device__ __forceinline__ float2 cmul(float2 a, float2 b) {
    return make_float2(fmaf(a.x, b.x, -a.y * b.y), fmaf(a.x, b.y, a.y * b.x));
}
__device__ __forceinline__ float2 cmadd(float2 acc, float2 a, float2 b) {
    acc.x = fmaf(a.x, b.x, fmaf(-a.y, b.y, acc.x));
    acc.y = fmaf(a.x, b.y, fmaf(a.y, b.x, acc.y));
    return acc;
}
__device__ __forceinline__ int dswz(int y) { return y ^ ((y >> 4) & 0xF); }

__device__ __forceinline__ void bfly(float2& a0, float2& a1,
                                     float2 E00, float2 E01, float2 E10, float2 E11) {
    float2 n0 = cmul(E00, a0); n0 = cmadd(n0, E01, a1);
    float2 n1 = cmul(E10, a0); n1 = cmadd(n1, E11, a1);
    a0 = n0; a1 = n1;
}

template<int P, int U, int NU>
__device__ __forceinline__ void coset_ld(float2* amp, const float2* st, int zb) {
    if constexpr (P == 0)      amp[U] = st[zb ^ IC<(int)CD.swzM0[U]>::v];
    else if constexpr (P == 1) amp[U] = st[zb ^ IC<(int)CD.swzM1[U]>::v];
    else                       amp[U] = st[zb ^ IC<(int)CD.swzM2[U]>::v];
    if constexpr (U + 1 < NU) coset_ld<P, U + 1, NU>(amp, st, zb);
}
template<int P, int U, int NU>
__device__ __forceinline__ void coset_st(const float2* amp, float2* st, int zb) {
    if constexpr (P == 0)      st[zb ^ IC<(int)CD.swzM0[U]>::v] = amp[U];
    else if constexpr (P == 1) st[zb ^ IC<(int)CD.swzM1[U]>::v] = amp[U];
    else                       st[zb ^ IC<(int)CD.swzM2[U]>::v] = amp[U];
    if constexpr (U + 1 < NU) coset_st<P, U + 1, NU>(amp, st, zb);
}

template<int W>
__device__ __forceinline__ int signw(int r) {
    int v = (__popc(r & IC<(int)CD.cw[W]>::v) & 1) << W;
    if constexpr (W > 0) v |= signw<W - 1>(r);
    return v;
}
template<int W>
__device__ __forceinline__ void accw(float (&acc)[NW], int swv, const float (&Wv)[16]) {
    const float tv = Wv[IC<CD.fw[W]>::v];
    const unsigned sg = (((unsigned)swv >> W) & 1u) << 31;
    acc[W] += __int_as_float(__float_as_int(tv) ^ sg);
    if constexpr (W < NW - 1) accw<W + 1>(acc, swv, Wv);
}

// ==================== kernel ====================
__global__ __launch_bounds__(NTHREADS, 1)
void qsim_kernel(const float* __restrict__ x, const float* __restrict__ params,
                 float* __restrict__ out)
{
    extern __shared__ float2 state[];      // 16384 float2 = 128 KB
    __shared__ float2 m0V[NW][4];          // layer-0 fused 2x2 (incl. x)
    __shared__ float2 m1V[NW][4];          // layer-1 fused 2x2
    __shared__ float2 GCs[2][32][2];       // p0 tables: [r8][u][parity]
    __shared__ float wsum[NWARPS][NW];

    const int tid = threadIdx.x;
    const int b = blockIdx.x;

    // ---- fused gate matrices: M = RX * RZ * RY (layer 0 folds in x)
    if (tid < 2 * NW) {
        const int l = tid / NW, w = tid % NW;
        const float* pp = params + (l * NW + w) * 3;
        float th = pp[0] + (l == 0 ? x[b * NW + w] : 0.0f);
        float s, c;   sincosf(0.5f * th, &s, &c);
        float sz, cz; sincosf(0.5f * pp[1], &sz, &cz);
        float sx, cx; sincosf(0.5f * pp[2], &sx, &cx);
        float2 r00 = make_float2(c * cz, -c * sz);
        float2 r01 = make_float2(-s * cz, s * sz);
        float2 r10 = make_float2(s * cz, s * sz);
        float2 r11 = make_float2(c * cz, c * sz);
        float2 (*dst)[4] = (l == 0) ? m0V : m1V;
        dst[w][0] = make_float2(cx * r00.x + sx * r10.y, cx * r00.y - sx * r10.x);
        dst[w][1] = make_float2(cx * r01.x + sx * r11.y, cx * r01.y - sx * r11.x);
        dst[w][2] = make_float2(sx * r00.y + cx * r10.x, -sx * r00.x + cx * r10.y);
        dst[w][3] = make_float2(sx * r01.y + cx * r11.x, -sx * r01.x + cx * r11.y);
    }
    __syncthreads();

    // ---- p0 tables: G_p * (encoding coset vector), 4 variants (r8, parity)
    //      computed by 4 warps with shuffle butterflies.
    if (tid < 128) {
        const int u = tid & 31, v = tid >> 5;
        const int r8 = v & 1, p = v >> 1;
        const int u0 = u & 1, u1 = (u >> 1) & 1, u2 = (u >> 2) & 1,
                  u3 = (u >> 3) & 1, u4 = (u >> 4) & 1;
        // encoding product over bits 8..13 of y for this coset coordinate
        float2 c = m0V[4][(u0 ^ u1) ? 2 : 0];      // bit 9  -> wire 4
        c = cmul(c, m0V[3][(u1 ^ u2) ? 2 : 0]);    // bit 10 -> wire 3
        c = cmul(c, m0V[2][(u2 ^ u3) ? 2 : 0]);    // bit 11 -> wire 2
        c = cmul(c, m0V[1][(u3 ^ u4) ? 2 : 0]);    // bit 12 -> wire 1
        c = cmul(c, m0V[0][u4 ? 2 : 0]);           // bit 13 -> wire 0
        c = cmul(c, m0V[5][(r8 ^ u0) ? 2 : 0]);    // bit 8  -> wire 5
        // five layer-1 butterfly stages on u-space (wires 4,3,2,1 then 0)
#pragma unroll
        for (int i = 0; i < 5; ++i) {
            const int w = (i < 4) ? (4 - i) : 0;
            const int sw = (i == 4 && p) ? 3 : 0;  // stage-4 label swap for parity=1
            float2 other;
            other.x = __shfl_xor_sync(0xFFFFFFFFu, c.x, 1 << i);
            other.y = __shfl_xor_sync(0xFFFFFFFFu, c.y, 1 << i);
            const bool hi = (u >> i) & 1;
            const float2 a0 = hi ? other : c;
            const float2 a1 = hi ? c : other;
            const float2 Er0 = m1V[w][(hi ? 2 : 0) ^ sw];
            const float2 Er1 = m1V[w][(hi ? 3 : 1) ^ sw];
            float2 n = cmul(Er0, a0); n = cmadd(n, Er1, a1);
            c = n;
        }
        GCs[r8][u][p] = c;
    }
    __syncthreads();

    // ---- Pass 0: amp[u] = P_r * GCs[r8][u][parity(r)] (all gate work hoisted)
    {
        const int r = tid;                       // complement bits 0..8
        const int zb = dswz(r);
        const int r8 = (r >> 8) & 1;
        const int p = __popc(r) & 1;
        // tree product over bits 0..7 (wires 13..6)
        float2 q0 = cmul(m0V[13][(r & 1)   ? 2 : 0], m0V[12][(r & 2)   ? 2 : 0]);
        float2 q1 = cmul(m0V[11][(r & 4)   ? 2 : 0], m0V[10][(r & 8)   ? 2 : 0]);
        float2 q2 = cmul(m0V[9][(r & 16)   ? 2 : 0], m0V[8][(r & 32)   ? 2 : 0]);
        float2 q3 = cmul(m0V[7][(r & 64)   ? 2 : 0], m0V[6][(r & 128)  ? 2 : 0]);
        const float2 P = cmul(cmul(q0, q1), cmul(q2, q3));
        const float2* tab = &GCs[r8][0][p];      // stride 2 float2 per u
        float2 amp[32];
#pragma unroll
        for (int u = 0; u < 32; ++u) amp[u] = cmul(P, tab[2 * u]);
        coset_st<0, 0, 32>(amp, state, zb);
    }
    __syncthreads();

    // ---- Pass 1: gates on virtual bits 4..8 (wires 9..5)
    {
        const int r = (tid & 0xF) | ((tid >> 4) << 9);   // bits 0..3, 9..13
        const int zb = dswz(r);
        const int sw = (__popc(tid >> 4) & 1) ? 3 : 0;   // shared by all 5 stages
        float2 amp[32];
        coset_ld<1, 0, 32>(amp, state, zb);
#pragma unroll
        for (int i = 0; i < 5; ++i) {
            const int w = 9 - i;
            const float2 E00 = m1V[w][0 ^ sw], E01 = m1V[w][1 ^ sw];
            const float2 E10 = m1V[w][2 ^ sw], E11 = m1V[w][3 ^ sw];
#pragma unroll
            for (int u = 0; u < 32; ++u) {
                if (u & (1 << i)) continue;
                bfly(amp[u], amp[u | (1 << i)], E00, E01, E10, E11);
            }
        }
        coset_st<1, 0, 32>(amp, state, zb);
    }
    __syncthreads();

    // ---- Pass 2: gates on virtual bits 0..3 (wires 13..10) fused w/ measurement
    float acc[NW];
#pragma unroll
    for (int w = 0; w < NW; ++w) acc[w] = 0.0f;
    {
        const int swv0 = signw<NW - 1>(tid << 4);
#pragma unroll
        for (int it = 0; it < 2; ++it) {
            const int r = (tid << 4) | (it << 13);       // bits 4..13
            const int zb = dswz(r);
            const int sw = ((__popc(tid) + it) & 1) ? 3 : 0;
            float2 amp[16];
            coset_ld<2, 0, 16>(amp, state, zb);
#pragma unroll
            for (int i = 0; i < 4; ++i) {
                const int w = 13 - i;
                const float2 E00 = m1V[w][0 ^ sw], E01 = m1V[w][1 ^ sw];
                const float2 E10 = m1V[w][2 ^ sw], E11 = m1V[w][3 ^ sw];
#pragma unroll
                for (int u = 0; u < 16; ++u) {
                    if (u & (1 << i)) continue;
                    bfly(amp[u], amp[u | (1 << i)], E00, E01, E10, E11);
                }
            }
            float Wv[16];
#pragma unroll
            for (int u = 0; u < 16; ++u)
                Wv[u] = fmaf(amp[u].x, amp[u].x, amp[u].y * amp[u].y);
#pragma unroll
            for (int d = 1; d < 16; d <<= 1) {
#pragma unroll
                for (int u = 0; u < 16; ++u) {
                    if (u & d) continue;
                    const float a = Wv[u], bb = Wv[u | d];
                    Wv[u] = a + bb; Wv[u | d] = a - bb;
                }
            }
            const int swv = it ? (swv0 ^ IC<CD.dw13>::v) : swv0;
            accw<0>(acc, swv, Wv);
        }
    }

    // ---- block reduction of 14 accumulators
    const int lane = tid & 31, warp = tid >> 5;
#pragma unroll
    for (int w = 0; w < NW; ++w) {
        float v = acc[w];
#pragma unroll
        for (int off = 16; off; off >>= 1) v += __shfl_down_sync(0xFFFFFFFFu, v, off);
        if (lane == 0) wsum[warp][w] = v;
    }
    __syncthreads();
    if (tid < NW) {
        float s = 0.0f;
#pragma unroll
        for (int q = 0; q < NWARPS; ++q) s += wsum[q][tid];
        out[b * NW + tid] = s;
    }
}

// ==================== host side ====================
extern "C" void kernel_launch(void* const* d_in, const int* in_sizes, int n_in,
                              void* d_out, int out_size)
{
    int i_x = 0, i_p = 1;
    if (n_in >= 2 && in_sizes[0] == 2 * NW * 3) { i_x = 1; i_p = 0; }
    const float* x = (const float*)d_in[i_x];
    const float* params = (const float*)d_in[i_p];
    float* out = (float*)d_out;

    const int batch = in_sizes[i_x] / NW;

    cudaFuncSetAttribute(qsim_kernel, cudaFuncAttributeMaxDynamicSharedMemorySize,
                         NSTATE * sizeof(float2));
    qsim_kernel<<<batch, NTHREADS, NSTATE * sizeof(float2)>>>(x, params, out);
}

// round 12
// speedup vs baseline: 1.8221x; 1.1855x over previous
#include <cuda_runtime.h>

#define NW 14
#define NSTATE (1 << NW)        // 16384 amplitudes
#define NTHREADS 512
#define NWARPS (NTHREADS / 32)

// ==================== compile-time GF(2) machinery ====================
struct CT {
    unsigned rowA[NW];      // rows of A
    unsigned colAinv[NW];   // columns of A^-1 (pair masks)
    unsigned cw[NW];        // rowA2[13-w]: measurement parity masks per wire
    unsigned swzP0[32];     // swz2(combos of colAinv[5..9])  (p0 store offsets)
    unsigned swzF5[32];     // swz2(combos of colAinv[0..4])  (final-pass offsets)
    int fw5[NW];            // 5-bit WHT frequency per wire
};

constexpr unsigned ctswz2(unsigned y) { return y ^ ((y >> 5) & 0xFu); }
constexpr int ctpar(unsigned v) { int p = 0; while (v) { p ^= (int)(v & 1u); v >>= 1; } return p; }

constexpr CT buildCT() {
    CT g{};
    unsigned R[NW] = {};
    for (int j = 0; j < NW; ++j) R[j] = 1u << j;
    // CNOT(w,w+1) w=0..12 then CNOT(13,0); wire w <-> bit 13-w
    for (int w = 0; w < NW - 1; ++w) R[NW - 2 - w] ^= R[NW - 1 - w];
    R[NW - 1] ^= R[0];
    for (int j = 0; j < NW; ++j) g.rowA[j] = R[j];
    unsigned aug[NW] = {};
    for (int j = 0; j < NW; ++j) aug[j] = R[j] | (1u << (NW + j));
    for (int col = 0; col < NW; ++col) {
        int piv = -1;
        for (int rr = col; rr < NW; ++rr)
            if ((aug[rr] >> col) & 1u) { piv = rr; break; }
        unsigned t = aug[col]; aug[col] = aug[piv]; aug[piv] = t;
        for (int rr = 0; rr < NW; ++rr)
            if (rr != col && ((aug[rr] >> col) & 1u)) aug[rr] ^= aug[col];
    }
    for (int bc = 0; bc < NW; ++bc) {
        unsigned mc = 0;
        for (int j = 0; j < NW; ++j) mc |= ((aug[j] >> (NW + bc)) & 1u) << j;
        g.colAinv[bc] = mc;
    }
    for (int w = 0; w < NW; ++w) {
        const int k = 13 - w;
        unsigned rr = 0;
        for (int j = 0; j < NW; ++j) if ((R[k] >> j) & 1u) rr ^= R[j];
        g.cw[w] = rr;
    }
    for (unsigned u = 0; u < 32; ++u) {
        unsigned M0 = 0, M1 = 0;
        for (int i = 0; i < 5; ++i) if ((u >> i) & 1u) { M0 ^= g.colAinv[5 + i]; M1 ^= g.colAinv[i]; }
        g.swzP0[u] = ctswz2(M0);
        g.swzF5[u] = ctswz2(M1);
    }
    for (int w = 0; w < NW; ++w) {
        int f = 0;
        for (int i = 0; i < 5; ++i) f |= ctpar(g.colAinv[i] & g.cw[w]) << i;
        g.fw5[w] = f;
    }
    return g;
}
constexpr CT CD = buildCT();

// ---- compile-time validation ----
constexpr bool checkPass(unsigned posmask, int b0, int k) {
    unsigned v[NW] = {}; int n = 0;
    for (int p = 0; p < NW; ++p) if ((posmask >> p) & 1u) v[n++] = 1u << p;
    for (int i = 0; i < k; ++i) v[n++] = CD.colAinv[b0 + i];
    if (n != NW) return false;
    int rank = 0;
    for (int bit = 0; bit < NW; ++bit) {
        int piv = -1;
        for (int i = rank; i < NW; ++i) if ((v[i] >> bit) & 1u) { piv = i; break; }
        if (piv < 0) continue;
        unsigned t = v[rank]; v[rank] = v[piv]; v[piv] = t;
        for (int i = 0; i < NW; ++i) if (i != rank && ((v[i] >> bit) & 1u)) v[i] ^= v[rank];
        ++rank;
    }
    return rank == NW;
}
static_assert(checkPass(0x001F, 5, 9), "p0 transversal (bits 0..4 + gates 5..13)");
static_assert(checkPass(0x3FE0, 0, 5), "final transversal (bits 5..13 + gates 0..4)");
// pair-mask chain structure (encoding factorization assumption)
static_assert(CD.colAinv[5] == 0x30 && CD.colAinv[6] == 0x60 && CD.colAinv[7] == 0xC0 &&
              CD.colAinv[8] == 0x180 && CD.colAinv[9] == 0x300 && CD.colAinv[10] == 0x600 &&
              CD.colAinv[11] == 0xC00 && CD.colAinv[12] == 0x1800 && CD.colAinv[13] == 0x3000,
              "chain masks");
// base parities: gates 5..12 unswapped over bits 0..4; gate 13 swaps by parity(r)
static_assert((CD.rowA[5] & 0x1F) == 0 && (CD.rowA[6] & 0x1F) == 0 && (CD.rowA[7] & 0x1F) == 0 &&
              (CD.rowA[8] & 0x1F) == 0 && (CD.rowA[9] & 0x1F) == 0 && (CD.rowA[10] & 0x1F) == 0 &&
              (CD.rowA[11] & 0x1F) == 0 && (CD.rowA[12] & 0x1F) == 0 &&
              (CD.rowA[13] & 0x1F) == 0x1F, "table bases");
// final-pass gates 0..4: all bases = parity(r over bits 5..13)
static_assert((CD.rowA[0] & 0x3FE0) == 0x3FE0 && (CD.rowA[1] & 0x3FE0) == 0x3FE0 &&
              (CD.rowA[2] & 0x3FE0) == 0x3FE0 && (CD.rowA[3] & 0x3FE0) == 0x3FE0 &&
              (CD.rowA[4] & 0x3FE0) == 0x3FE0, "final bases");

template<int V> struct IC { static constexpr int v = V; };

// ==================== device helpers ====================
__device__ __forceinline__ float2 cmul(float2 a, float2 b) {
    return make_float2(fmaf(a.x, b.x, -a.y * b.y), fmaf(a.x, b.y, a.y * b.x));
}
__device__ __forceinline__ float2 cmadd(float2 acc, float2 a, float2 b) {
    acc.x = fmaf(a.x, b.x, fmaf(-a.y, b.y, acc.x));
    acc.y = fmaf(a.x, b.y, fmaf(a.y, b.x, acc.y));
    return acc;
}
__device__ __forceinline__ int dswz2(int y) { return y ^ ((y >> 5) & 0xF); }

__device__ __forceinline__ void bfly(float2& a0, float2& a1,
                                     float2 E00, float2 E01, float2 E10, float2 E11) {
    float2 n0 = cmul(E00, a0); n0 = cmadd(n0, E01, a1);
    float2 n1 = cmul(E10, a0); n1 = cmadd(n1, E11, a1);
    a0 = n0; a1 = n1;
}

// p0 store: state[zb ^ swzP0[U]] = P * tab[4U]
template<int U>
__device__ __forceinline__ void p0_store(float2* st, int zb, float2 P, const float2* tab) {
    st[zb ^ IC<(int)CD.swzP0[U]>::v] = cmul(P, tab[4 * U]);
    if constexpr (U < 31) p0_store<U + 1>(st, zb, P, tab);
}
// final-pass load
template<int U>
__device__ __forceinline__ void f_load(float2 (&amp)[32], const float2* st, int zb) {
    amp[U] = st[zb ^ IC<(int)CD.swzF5[U]>::v];
    if constexpr (U < 31) f_load<U + 1>(amp, st, zb);
}

template<int W>
__device__ __forceinline__ int signw(int r) {
    int v = (__popc(r & IC<(int)CD.cw[W]>::v) & 1) << W;
    if constexpr (W > 0) v |= signw<W - 1>(r);
    return v;
}
template<int W>
__device__ __forceinline__ void accw(float (&acc)[NW], int swv, const float (&Wv)[32]) {
    const float tv = Wv[IC<CD.fw5[W]>::v];
    const unsigned sg = (((unsigned)swv >> W) & 1u) << 31;
    acc[W] += __int_as_float(__float_as_int(tv) ^ sg);
    if constexpr (W < NW - 1) accw<W + 1>(acc, swv, Wv);
}

// ==================== kernel ====================
__global__ __launch_bounds__(NTHREADS, 1)
void qsim_kernel(const float* __restrict__ x, const float* __restrict__ params,
                 float* __restrict__ out)
{
    extern __shared__ float2 state[];      // 16384 float2 = 128 KB
    __shared__ float2 m0V[NW][4];          // layer-0 fused 2x2 (incl. x)
    __shared__ float2 m1V[NW][4];          // layer-1 fused 2x2
    __shared__ float2 T[512][4];           // hoisted-gate table: [u][r4*2+p]
    __shared__ float wsum[NWARPS][NW];

    const int tid = threadIdx.x;
    const int b = blockIdx.x;

    // ---- fused gate matrices: M = RX * RZ * RY (layer 0 folds in x)
    if (tid < 2 * NW) {
        const int l = tid / NW, w = tid % NW;
        const float* pp = params + (l * NW + w) * 3;
        float th = pp[0] + (l == 0 ? x[b * NW + w] : 0.0f);
        float s, c;   sincosf(0.5f * th, &s, &c);
        float sz, cz; sincosf(0.5f * pp[1], &sz, &cz);
        float sx, cx; sincosf(0.5f * pp[2], &sx, &cx);
        float2 r00 = make_float2(c * cz, -c * sz);
        float2 r01 = make_float2(-s * cz, s * sz);
        float2 r10 = make_float2(s * cz, s * sz);
        float2 r11 = make_float2(c * cz, c * sz);
        float2 (*dst)[4] = (l == 0) ? m0V : m1V;
        dst[w][0] = make_float2(cx * r00.x + sx * r10.y, cx * r00.y - sx * r10.x);
        dst[w][1] = make_float2(cx * r01.x + sx * r11.y, cx * r01.y - sx * r11.x);
        dst[w][2] = make_float2(sx * r00.y + cx * r10.x, -sx * r00.x + cx * r10.y);
        dst[w][3] = make_float2(sx * r01.y + cx * r11.x, -sx * r01.x + cx * r11.y);
    }
    __syncthreads();

    // ---- Table build: encoding coset vector over y bits 4..13, then 9 gate
    //      stages (wires 8..0) in u-space.  Variants: r4 (encoding) x p (gate-13 swap).
    {
        const int u = tid;
        const int u0 = u & 1, u1 = (u >> 1) & 1, u2 = (u >> 2) & 1, u3 = (u >> 3) & 1,
                  u4 = (u >> 4) & 1, u5 = (u >> 5) & 1, u6 = (u >> 6) & 1,
                  u7 = (u >> 7) & 1, u8 = (u >> 8) & 1;
        float2 cc = m0V[8][(u0 ^ u1) ? 2 : 0];          // y5 -> wire 8
        cc = cmul(cc, m0V[7][(u1 ^ u2) ? 2 : 0]);       // y6 -> wire 7
        cc = cmul(cc, m0V[6][(u2 ^ u3) ? 2 : 0]);       // y7 -> wire 6
        cc = cmul(cc, m0V[5][(u3 ^ u4) ? 2 : 0]);       // y8 -> wire 5
        cc = cmul(cc, m0V[4][(u4 ^ u5) ? 2 : 0]);       // y9 -> wire 4
        cc = cmul(cc, m0V[3][(u5 ^ u6) ? 2 : 0]);       // y10 -> wire 3
        cc = cmul(cc, m0V[2][(u6 ^ u7) ? 2 : 0]);       // y11 -> wire 2
        cc = cmul(cc, m0V[1][(u7 ^ u8) ? 2 : 0]);       // y12 -> wire 1
        cc = cmul(cc, m0V[0][u8 ? 2 : 0]);              // y13 -> wire 0
        T[u][0] = cmul(m0V[9][u0 ? 2 : 0], cc);         // y4 -> wire 9, r4=0
        T[u][2] = cmul(m0V[9][u0 ? 0 : 2], cc);         // r4=1
    }
    // stages 0..7: gate on u-bit s = wire 8-s, no label swap
    for (int s = 0; s < 8; ++s) {
        __syncthreads();
        const int a = tid & 1, pu = tid >> 1;
        const int u0p = ((pu >> s) << (s + 1)) | (pu & ((1 << s) - 1));
        const int u1p = u0p | (1 << s);
        float2 A0 = T[u0p][a * 2], A1 = T[u1p][a * 2];
        const int w = 8 - s;
        bfly(A0, A1, m1V[w][0], m1V[w][1], m1V[w][2], m1V[w][3]);
        T[u0p][a * 2] = A0; T[u1p][a * 2] = A1;
    }
    // final stage: gate on u-bit 8 = wire 0; fork p variants (label swap)
    __syncthreads();
    {
        const int a = tid & 1, pu = tid >> 1;
        const float2 A0 = T[pu][a * 2], A1 = T[pu | 256][a * 2];
        float2 n0 = cmul(m1V[0][0], A0); n0 = cmadd(n0, m1V[0][1], A1);
        float2 n1 = cmul(m1V[0][2], A0); n1 = cmadd(n1, m1V[0][3], A1);
        float2 s0 = cmul(m1V[0][3], A0); s0 = cmadd(s0, m1V[0][2], A1);
        float2 s1 = cmul(m1V[0][1], A0); s1 = cmadd(s1, m1V[0][0], A1);
        T[pu][a * 2] = n0; T[pu | 256][a * 2] = n1;
        T[pu][a * 2 + 1] = s0; T[pu | 256][a * 2 + 1] = s1;
    }
    __syncthreads();

    // ---- Pass 0: state[y] = P_r * T[u][v]  (9 of 14 gates already applied)
    {
        const int r = tid & 31, h = tid >> 5;
        const int pp = __popc(r) & 1;
        const int r4 = (r >> 4) & 1;
        const int v = r4 * 2 + pp;
        const float2 q0 = cmul(m0V[13][(r & 1) ? 2 : 0], m0V[12][(r & 2) ? 2 : 0]);
        const float2 q1 = cmul(m0V[11][(r & 4) ? 2 : 0], m0V[10][(r & 8) ? 2 : 0]);
        const float2 P = cmul(q0, q1);
        int Mh = 0;
        if (h & 1) Mh ^= IC<(int)CD.colAinv[10]>::v;
        if (h & 2) Mh ^= IC<(int)CD.colAinv[11]>::v;
        if (h & 4) Mh ^= IC<(int)CD.colAinv[12]>::v;
        if (h & 8) Mh ^= IC<(int)CD.colAinv[13]>::v;
        const int zb = dswz2(r ^ Mh);
        const float2* tab = &T[h * 32][0] + v;
        p0_store<0>(state, zb, P, tab);
    }
    __syncthreads();

    // ---- Final pass: gates on virtual bits 0..4 (wires 13..9) + measurement
    float acc[NW];
#pragma unroll
    for (int w = 0; w < NW; ++w) acc[w] = 0.0f;
    {
        const int r = tid << 5;                       // coset rep: bits 5..13
        const int zb = dswz2(r);
        const int sw = (__popc(tid) & 1) ? 3 : 0;     // shared by all 5 gates
        float2 amp[32];
        f_load<0>(amp, state, zb);
#pragma unroll
        for (int i = 0; i < 5; ++i) {
            const int w = 13 - i;
            const float2 E00 = m1V[w][0 ^ sw], E01 = m1V[w][1 ^ sw];
            const float2 E10 = m1V[w][2 ^ sw], E11 = m1V[w][3 ^ sw];
#pragma unroll
            for (int u = 0; u < 32; ++u) {
                if (u & (1 << i)) continue;
                bfly(amp[u], amp[u | (1 << i)], E00, E01, E10, E11);
            }
        }
        float Wv[32];
#pragma unroll
        for (int u = 0; u < 32; ++u)
            Wv[u] = fmaf(amp[u].x, amp[u].x, amp[u].y * amp[u].y);
        // 32-point WHT: Wv[f] = sum_u (-1)^{popc(f&u)} p[u]
#pragma unroll
        for (int d = 1; d < 32; d <<= 1) {
#pragma unroll
            for (int u = 0; u < 32; ++u) {
                if (u & d) continue;
                const float a = Wv[u], bb = Wv[u | d];
                Wv[u] = a + bb; Wv[u | d] = a - bb;
            }
        }
        const int swv = signw<NW - 1>(r);
        accw<0>(acc, swv, Wv);
    }

    // ---- block reduction of 14 accumulators
    const int lane = tid & 31, warp = tid >> 5;
#pragma unroll
    for (int w = 0; w < NW; ++w) {
        float v = acc[w];
#pragma unroll
        for (int off = 16; off; off >>= 1) v += __shfl_down_sync(0xFFFFFFFFu, v, off);
        if (lane == 0) wsum[warp][w] = v;
    }
    __syncthreads();
    if (tid < NW) {
        float s = 0.0f;
#pragma unroll
        for (int q = 0; q < NWARPS; ++q) s += wsum[q][tid];
        out[b * NW + tid] = s;
    }
}

// ==================== host side ====================
extern "C" void kernel_launch(void* const* d_in, const int* in_sizes, int n_in,
                              void* d_out, int out_size)
{
    int i_x = 0, i_p = 1;
    if (n_in >= 2 && in_sizes[0] == 2 * NW * 3) { i_x = 1; i_p = 0; }
    const float* x = (const float*)d_in[i_x];
    const float* params = (const float*)d_in[i_p];
    float* out = (float*)d_out;

    const int batch = in_sizes[i_x] / NW;

    cudaFuncSetAttribute(qsim_kernel, cudaFuncAttributeMaxDynamicSharedMemorySize,
                         NSTATE * sizeof(float2));
    qsim_kernel<<<batch, NTHREADS, NSTATE * sizeof(float2)>>>(x, params, out);
}